// round 2
// baseline (speedup 1.0000x reference)
#include <cuda_runtime.h>
#include <cuda_bf16.h>
#include <cstdint>
#include <math.h>

#define NNODE 8192
#define DIN   512
#define DLAT  128
#define KDIM  512   // 4*DLAT packed features

static const int OUT_NN = NNODE * NNODE;           // 67108864
static const int OUT_NL = NNODE * DLAT;            // 1048576

// ---------------- scratch (device globals; no allocation allowed) ----------
__device__ float g_T[3][DIN][DLAT];                // softmaxed transforms
__device__ float g_zd[NNODE * DLAT];
__device__ float g_ig[NNODE * DLAT];               // 1/(gd+SMALL)
__device__ float g_id[NNODE * DLAT];               // 1/(dd+SMALL)
__device__ __nv_bfloat16 g_U[NNODE * KDIM];
__device__ __nv_bfloat16 g_V[NNODE * KDIM];
__device__ float g_c[NNODE];
__device__ float g_d[NNODE];

// ---------------- K1: column softmax of the three W matrices ---------------
__global__ void softmax_cols(const float* __restrict__ Wz,
                             const float* __restrict__ Wg,
                             const float* __restrict__ Wd) {
    int mat = blockIdx.x >> 7;        // 0..2
    int col = blockIdx.x & 127;
    const float* W = (mat == 0) ? Wz : (mat == 1) ? Wg : Wd;
    int t = threadIdx.x;              // 128 threads
    __shared__ float red[128];

    float v[4];
#pragma unroll
    for (int r = 0; r < 4; r++) v[r] = W[(t + r * 128) * DLAT + col];

    float m = fmaxf(fmaxf(v[0], v[1]), fmaxf(v[2], v[3]));
    red[t] = m; __syncthreads();
    for (int s = 64; s > 0; s >>= 1) {
        if (t < s) red[t] = fmaxf(red[t], red[t + s]);
        __syncthreads();
    }
    m = red[0]; __syncthreads();

    float e[4], sum = 0.f;
#pragma unroll
    for (int r = 0; r < 4; r++) { e[r] = expf(v[r] - m); sum += e[r]; }
    red[t] = sum; __syncthreads();
    for (int s = 64; s > 0; s >>= 1) {
        if (t < s) red[t] += red[t + s];
        __syncthreads();
    }
    float inv = 1.f / red[0];
#pragma unroll
    for (int r = 0; r < 4; r++) g_T[mat][t + r * 128][col] = e[r] * inv;
}

// ---------------- K2a: zd / gd / dd GEMMs (fp32 SIMT) ----------------------
// grid (NNODE/64, 3), 256 threads. BM=64, BN=128, BK=32, micro 4x(4+4).
__global__ __launch_bounds__(256) void gemm_small(const float* __restrict__ z,
                                                  const float* __restrict__ gamma,
                                                  const float* __restrict__ delta,
                                                  float* __restrict__ out) {
    __shared__ float As[32][65];      // [k][m] transposed
    __shared__ float Bs[32][128];

    int which = blockIdx.y;
    const float* A = (which == 0) ? z : (which == 1) ? gamma : delta;
    const float* B = &g_T[which][0][0];
    int r0 = blockIdx.x * 64;

    int tid = threadIdx.x;
    int ty = tid >> 4, tx = tid & 15;

    float acc[4][8];
#pragma unroll
    for (int i = 0; i < 4; i++)
#pragma unroll
        for (int j = 0; j < 8; j++) acc[i][j] = 0.f;

    for (int kc = 0; kc < DIN / 32; kc++) {
        // load A tile 64x32 -> transposed smem
#pragma unroll
        for (int it = 0; it < 2; it++) {
            int linear = tid + it * 256;          // 0..511
            int arow = linear >> 3, ac4 = linear & 7;
            float4 va = *reinterpret_cast<const float4*>(
                &A[(r0 + arow) * DIN + kc * 32 + ac4 * 4]);
            As[ac4 * 4 + 0][arow] = va.x;
            As[ac4 * 4 + 1][arow] = va.y;
            As[ac4 * 4 + 2][arow] = va.z;
            As[ac4 * 4 + 3][arow] = va.w;
        }
        // load B tile 32x128
#pragma unroll
        for (int it = 0; it < 4; it++) {
            int linear = tid + it * 256;          // 0..1023
            int brow = linear >> 5, bc4 = linear & 31;
            *reinterpret_cast<float4*>(&Bs[brow][bc4 * 4]) =
                *reinterpret_cast<const float4*>(&B[(kc * 32 + brow) * DLAT + bc4 * 4]);
        }
        __syncthreads();

#pragma unroll
        for (int kk = 0; kk < 32; kk++) {
            float a[4];
#pragma unroll
            for (int i = 0; i < 4; i++) a[i] = As[kk][ty * 4 + i];
            float4 b0 = *reinterpret_cast<float4*>(&Bs[kk][tx * 4]);
            float4 b1 = *reinterpret_cast<float4*>(&Bs[kk][64 + tx * 4]);
#pragma unroll
            for (int i = 0; i < 4; i++) {
                acc[i][0] = fmaf(a[i], b0.x, acc[i][0]);
                acc[i][1] = fmaf(a[i], b0.y, acc[i][1]);
                acc[i][2] = fmaf(a[i], b0.z, acc[i][2]);
                acc[i][3] = fmaf(a[i], b0.w, acc[i][3]);
                acc[i][4] = fmaf(a[i], b1.x, acc[i][4]);
                acc[i][5] = fmaf(a[i], b1.y, acc[i][5]);
                acc[i][6] = fmaf(a[i], b1.z, acc[i][6]);
                acc[i][7] = fmaf(a[i], b1.w, acc[i][7]);
            }
        }
        __syncthreads();
    }

    // epilogue
#pragma unroll
    for (int i = 0; i < 4; i++) {
        int node = r0 + ty * 4 + i;
#pragma unroll
        for (int j = 0; j < 8; j++) {
            int col = (j < 4) ? (tx * 4 + j) : (64 + tx * 4 + (j - 4));
            int idx = node * DLAT + col;
            float v = acc[i][j];
            if (which == 0) {
                g_zd[idx] = v;
                out[OUT_NN + idx] = v;
            } else if (which == 1) {
                out[OUT_NN + OUT_NL + idx] = v;
                g_ig[idx] = 1.f / (v + 1e-16f);
            } else {
                out[OUT_NN + 2 * OUT_NL + idx] = v;
                g_id[idx] = 1.f / (v + 1e-16f);
            }
        }
    }
}

// ---------------- K2b: build U, V (bf16) and c, d ---------------------------
__global__ void prep_kernel(const float* __restrict__ pb,
                            const float* __restrict__ pwg,
                            const float* __restrict__ pwd) {
    int i = blockIdx.x;
    int k = threadIdx.x;   // 128
    float zd = g_zd[i * DLAT + k];
    float ig = g_ig[i * DLAT + k];
    float id = g_id[i * DLAT + k];
    float z2 = zd * zd;
    float bias = *pb, wg = *pwg, wd = *pwd;
    const float n = 8192.0f;

    g_U[i * KDIM + 0   + k] = __float2bfloat16_rn(-wg * n * ig);
    g_U[i * KDIM + 128 + k] = __float2bfloat16_rn(2.f * wg * n * zd * ig);
    g_U[i * KDIM + 256 + k] = __float2bfloat16_rn(-wd * n * z2);
    g_U[i * KDIM + 384 + k] = __float2bfloat16_rn(2.f * wd * n * zd);

    g_V[i * KDIM + 0   + k] = __float2bfloat16_rn(z2);
    g_V[i * KDIM + 128 + k] = __float2bfloat16_rn(zd);
    g_V[i * KDIM + 256 + k] = __float2bfloat16_rn(id);
    g_V[i * KDIM + 384 + k] = __float2bfloat16_rn(zd * id);

    float a = z2 * ig, b = z2 * id;
#pragma unroll
    for (int o = 16; o > 0; o >>= 1) {
        a += __shfl_down_sync(0xffffffffu, a, o);
        b += __shfl_down_sync(0xffffffffu, b, o);
    }
    __shared__ float sa[4], sb[4];
    if ((k & 31) == 0) { sa[k >> 5] = a; sb[k >> 5] = b; }
    __syncthreads();
    if (k == 0) {
        float A = sa[0] + sa[1] + sa[2] + sa[3];
        float Bv = sb[0] + sb[1] + sb[2] + sb[3];
        g_c[i] = bias - wg * n * A;
        g_d[i] = -wd * n * Bv;
    }
}

// ---------------- K3: 8192x8192x512 bf16 GEMM + sigmoid epilogue ------------
__device__ __forceinline__ void ldsm_x4(uint32_t& r0, uint32_t& r1,
                                        uint32_t& r2, uint32_t& r3, uint32_t addr) {
    asm volatile("ldmatrix.sync.aligned.m8n8.x4.shared.b16 {%0,%1,%2,%3}, [%4];\n"
                 : "=r"(r0), "=r"(r1), "=r"(r2), "=r"(r3) : "r"(addr));
}
__device__ __forceinline__ void ldsm_x2(uint32_t& r0, uint32_t& r1, uint32_t addr) {
    asm volatile("ldmatrix.sync.aligned.m8n8.x2.shared.b16 {%0,%1}, [%2];\n"
                 : "=r"(r0), "=r"(r1) : "r"(addr));
}
__device__ __forceinline__ void mma_bf16(float& c0, float& c1, float& c2, float& c3,
                                         uint32_t a0, uint32_t a1, uint32_t a2, uint32_t a3,
                                         uint32_t b0, uint32_t b1) {
    asm volatile("mma.sync.aligned.m16n8k16.row.col.f32.bf16.bf16.f32 "
                 "{%0,%1,%2,%3}, {%4,%5,%6,%7}, {%8,%9}, {%0,%1,%2,%3};\n"
                 : "+f"(c0), "+f"(c1), "+f"(c2), "+f"(c3)
                 : "r"(a0), "r"(a1), "r"(a2), "r"(a3), "r"(b0), "r"(b1));
}

// exact (cancellation-free) recompute for near-diagonal elements
__device__ __noinline__ float exact_x(int i, int j, float bias, float wg, float wd) {
    const float* zi = &g_zd[i * DLAT];
    const float* zj = &g_zd[j * DLAT];
    const float* gi = &g_ig[i * DLAT];
    const float* dj = &g_id[j * DLAT];
    float s = 0.f;
    for (int k = 0; k < DLAT; k++) {
        float d = zi[k] - zj[k];
        s = fmaf(d * d, wg * gi[k] + wd * dj[k], s);
    }
    return bias - 8192.0f * s;
}

#define SPAD 40   // smem row stride (elements); 20-bank row shift => conflict-free ldmatrix

__global__ __launch_bounds__(256) void pair_kernel(float* __restrict__ out,
                                                   const float* __restrict__ pb,
                                                   const float* __restrict__ pwg,
                                                   const float* __restrict__ pwd) {
    __shared__ __align__(16) __nv_bfloat16 sA[2][128][SPAD];
    __shared__ __align__(16) __nv_bfloat16 sB[2][128][SPAD];

    int tid = threadIdx.x;
    int lane = tid & 31, wid = tid >> 5;
    int warpM = wid >> 2, warpN = wid & 3;     // 2 x 4 warps, warp tile 64x32
    int i0 = blockIdx.y * 128, j0 = blockIdx.x * 128;

    float acc[4][4][4];
#pragma unroll
    for (int a = 0; a < 4; a++)
#pragma unroll
        for (int b = 0; b < 4; b++)
#pragma unroll
            for (int c = 0; c < 4; c++) acc[a][b][c] = 0.f;

    // global-load / smem-store lane mapping (2 uint4 per operand per thread)
    int lrow[2], lq[2];
#pragma unroll
    for (int it = 0; it < 2; it++) {
        int linear = tid + it * 256;
        lrow[it] = linear >> 2;
        lq[it] = linear & 3;
    }

    // ldmatrix lane offsets
    int a_m = (lane & 7) + ((lane >> 3) & 1) * 8;   // + warpM*64 + mf*16
    int a_k = ((lane >> 4) & 1) * 8;                // + ks*16
    int l16 = lane & 15;
    int b_n = l16 & 7;                              // + warpN*32 + nf*8
    int b_k = (l16 >> 3) * 8;                       // + ks*16

    uint4 ra[2], rb[2];

    // prologue: chunk 0
#pragma unroll
    for (int it = 0; it < 2; it++) {
        ra[it] = *reinterpret_cast<const uint4*>(&g_U[(i0 + lrow[it]) * KDIM + lq[it] * 8]);
        rb[it] = *reinterpret_cast<const uint4*>(&g_V[(j0 + lrow[it]) * KDIM + lq[it] * 8]);
    }
#pragma unroll
    for (int it = 0; it < 2; it++) {
        __nv_bfloat16* pa = &sA[0][lrow[it]][lq[it] * 8];
        __nv_bfloat16* pbm = &sB[0][lrow[it]][lq[it] * 8];
        *reinterpret_cast<uint2*>(pa)      = make_uint2(ra[it].x, ra[it].y);
        *reinterpret_cast<uint2*>(pa + 4)  = make_uint2(ra[it].z, ra[it].w);
        *reinterpret_cast<uint2*>(pbm)     = make_uint2(rb[it].x, rb[it].y);
        *reinterpret_cast<uint2*>(pbm + 4) = make_uint2(rb[it].z, rb[it].w);
    }
    __syncthreads();

    const int NCHUNK = KDIM / 32;   // 16
#pragma unroll 1
    for (int kc = 0; kc < NCHUNK; kc++) {
        if (kc < NCHUNK - 1) {
            int koff = (kc + 1) * 32;
#pragma unroll
            for (int it = 0; it < 2; it++) {
                ra[it] = *reinterpret_cast<const uint4*>(
                    &g_U[(i0 + lrow[it]) * KDIM + koff + lq[it] * 8]);
                rb[it] = *reinterpret_cast<const uint4*>(
                    &g_V[(j0 + lrow[it]) * KDIM + koff + lq[it] * 8]);
            }
        }

        // compute on buffer kc&1
        {
            int buf = kc & 1;
            uint32_t baseA = (uint32_t)__cvta_generic_to_shared(&sA[buf][0][0]);
            uint32_t baseB = (uint32_t)__cvta_generic_to_shared(&sB[buf][0][0]);
#pragma unroll
            for (int ks = 0; ks < 2; ks++) {
                uint32_t af[4][4], bf[4][2];
#pragma unroll
                for (int mf = 0; mf < 4; mf++) {
                    int mm = warpM * 64 + mf * 16 + a_m;
                    int kk = ks * 16 + a_k;
                    ldsm_x4(af[mf][0], af[mf][1], af[mf][2], af[mf][3],
                            baseA + (uint32_t)(mm * SPAD + kk) * 2u);
                }
#pragma unroll
                for (int nf = 0; nf < 4; nf++) {
                    int nn = warpN * 32 + nf * 8 + b_n;
                    int kk = ks * 16 + b_k;
                    ldsm_x2(bf[nf][0], bf[nf][1],
                            baseB + (uint32_t)(nn * SPAD + kk) * 2u);
                }
#pragma unroll
                for (int mf = 0; mf < 4; mf++)
#pragma unroll
                    for (int nf = 0; nf < 4; nf++)
                        mma_bf16(acc[mf][nf][0], acc[mf][nf][1], acc[mf][nf][2], acc[mf][nf][3],
                                 af[mf][0], af[mf][1], af[mf][2], af[mf][3],
                                 bf[nf][0], bf[nf][1]);
            }
        }

        if (kc < NCHUNK - 1) {
            int buf = (kc + 1) & 1;
#pragma unroll
            for (int it = 0; it < 2; it++) {
                __nv_bfloat16* pa = &sA[buf][lrow[it]][lq[it] * 8];
                __nv_bfloat16* pbm = &sB[buf][lrow[it]][lq[it] * 8];
                *reinterpret_cast<uint2*>(pa)      = make_uint2(ra[it].x, ra[it].y);
                *reinterpret_cast<uint2*>(pa + 4)  = make_uint2(ra[it].z, ra[it].w);
                *reinterpret_cast<uint2*>(pbm)     = make_uint2(rb[it].x, rb[it].y);
                *reinterpret_cast<uint2*>(pbm + 4) = make_uint2(rb[it].z, rb[it].w);
            }
        }
        __syncthreads();
    }

    // epilogue
    float bias = *pb, wg = *pwg, wd = *pwd;
    int lr = lane >> 2, lc = (lane & 3) * 2;
#pragma unroll
    for (int mf = 0; mf < 4; mf++) {
#pragma unroll
        for (int nf = 0; nf < 4; nf++) {
            int i1 = i0 + warpM * 64 + mf * 16 + lr;
            int j = j0 + warpN * 32 + nf * 8 + lc;
#pragma unroll
            for (int half = 0; half < 2; half++) {
                int i = i1 + half * 8;
                float ci = g_c[i];
                float x0 = acc[mf][nf][half * 2 + 0] + ci + g_d[j];
                float x1 = acc[mf][nf][half * 2 + 1] + ci + g_d[j + 1];
                if (x0 > -300.f) x0 = exact_x(i, j, bias, wg, wd);
                if (x1 > -300.f) x1 = exact_x(i, j + 1, bias, wg, wd);
                float2 r;
                r.x = 1.f / (1.f + expf(-x0));
                r.y = 1.f / (1.f + expf(-x1));
                *reinterpret_cast<float2*>(&out[(size_t)i * NNODE + j]) = r;
            }
        }
    }
}

// ---------------- launch -----------------------------------------------------
extern "C" void kernel_launch(void* const* d_in, const int* in_sizes, int n_in,
                              void* d_out, int out_size) {
    const float* z     = (const float*)d_in[0];
    const float* gamma = (const float*)d_in[1];
    const float* delta = (const float*)d_in[2];
    const float* Wz    = (const float*)d_in[3];
    const float* Wg    = (const float*)d_in[4];
    const float* Wd    = (const float*)d_in[5];
    const float* pb    = (const float*)d_in[6];
    const float* pwg   = (const float*)d_in[7];
    const float* pwd   = (const float*)d_in[8];
    float* out = (float*)d_out;

    softmax_cols<<<384, 128>>>(Wz, Wg, Wd);
    gemm_small<<<dim3(NNODE / 64, 3), 256>>>(z, gamma, delta, out);
    prep_kernel<<<NNODE, 128>>>(pb, pwg, pwd);
    pair_kernel<<<dim3(NNODE / 128, NNODE / 128), 256>>>(out, pb, pwg, pwd);
}

// round 3
// speedup vs baseline: 1.0012x; 1.0012x over previous
#include <cuda_runtime.h>
#include <cuda_bf16.h>
#include <cstdint>
#include <math.h>

#define NNODE 8192
#define DIN   512
#define DLAT  128
#define KDIM  512   // 4*DLAT packed features

static const int OUT_NN = NNODE * NNODE;           // 67108864
static const int OUT_NL = NNODE * DLAT;            // 1048576

// ---------------- scratch (device globals; no allocation allowed) ----------
__device__ float g_T[3][DIN][DLAT];                // softmaxed transforms
__device__ float g_zd[NNODE * DLAT];
__device__ float g_ig[NNODE * DLAT];               // 1/(gd+SMALL)
__device__ float g_id[NNODE * DLAT];               // 1/(dd+SMALL)
__device__ __nv_bfloat16 g_U[NNODE * KDIM];
__device__ __nv_bfloat16 g_V[NNODE * KDIM];
__device__ float g_c[NNODE];
__device__ float g_d[NNODE];

// ---------------- K1: column softmax of the three W matrices ---------------
__global__ void softmax_cols(const float* __restrict__ Wz,
                             const float* __restrict__ Wg,
                             const float* __restrict__ Wd) {
    int mat = blockIdx.x >> 7;        // 0..2
    int col = blockIdx.x & 127;
    const float* W = (mat == 0) ? Wz : (mat == 1) ? Wg : Wd;
    int t = threadIdx.x;              // 128 threads
    __shared__ float red[128];

    float v[4];
#pragma unroll
    for (int r = 0; r < 4; r++) v[r] = W[(t + r * 128) * DLAT + col];

    float m = fmaxf(fmaxf(v[0], v[1]), fmaxf(v[2], v[3]));
    red[t] = m; __syncthreads();
    for (int s = 64; s > 0; s >>= 1) {
        if (t < s) red[t] = fmaxf(red[t], red[t + s]);
        __syncthreads();
    }
    m = red[0]; __syncthreads();

    float e[4], sum = 0.f;
#pragma unroll
    for (int r = 0; r < 4; r++) { e[r] = expf(v[r] - m); sum += e[r]; }
    red[t] = sum; __syncthreads();
    for (int s = 64; s > 0; s >>= 1) {
        if (t < s) red[t] += red[t + s];
        __syncthreads();
    }
    float inv = 1.f / red[0];
#pragma unroll
    for (int r = 0; r < 4; r++) g_T[mat][t + r * 128][col] = e[r] * inv;
}

// ---------------- K2a: zd / gd / dd GEMMs (fp32 SIMT) ----------------------
// grid (NNODE/64, 3), 256 threads. BM=64, BN=128, BK=32, micro 4x(4+4).
__global__ __launch_bounds__(256) void gemm_small(const float* __restrict__ z,
                                                  const float* __restrict__ gamma,
                                                  const float* __restrict__ delta,
                                                  float* __restrict__ out) {
    __shared__ float As[32][65];      // [k][m] transposed
    __shared__ float Bs[32][128];

    int which = blockIdx.y;
    const float* A = (which == 0) ? z : (which == 1) ? gamma : delta;
    const float* B = &g_T[which][0][0];
    int r0 = blockIdx.x * 64;

    int tid = threadIdx.x;
    int ty = tid >> 4, tx = tid & 15;

    float acc[4][8];
#pragma unroll
    for (int i = 0; i < 4; i++)
#pragma unroll
        for (int j = 0; j < 8; j++) acc[i][j] = 0.f;

    for (int kc = 0; kc < DIN / 32; kc++) {
        // load A tile 64x32 -> transposed smem
#pragma unroll
        for (int it = 0; it < 2; it++) {
            int linear = tid + it * 256;          // 0..511
            int arow = linear >> 3, ac4 = linear & 7;
            float4 va = *reinterpret_cast<const float4*>(
                &A[(r0 + arow) * DIN + kc * 32 + ac4 * 4]);
            As[ac4 * 4 + 0][arow] = va.x;
            As[ac4 * 4 + 1][arow] = va.y;
            As[ac4 * 4 + 2][arow] = va.z;
            As[ac4 * 4 + 3][arow] = va.w;
        }
        // load B tile 32x128
#pragma unroll
        for (int it = 0; it < 4; it++) {
            int linear = tid + it * 256;          // 0..1023
            int brow = linear >> 5, bc4 = linear & 31;
            *reinterpret_cast<float4*>(&Bs[brow][bc4 * 4]) =
                *reinterpret_cast<const float4*>(&B[(kc * 32 + brow) * DLAT + bc4 * 4]);
        }
        __syncthreads();

#pragma unroll
        for (int kk = 0; kk < 32; kk++) {
            float a[4];
#pragma unroll
            for (int i = 0; i < 4; i++) a[i] = As[kk][ty * 4 + i];
            float4 b0 = *reinterpret_cast<float4*>(&Bs[kk][tx * 4]);
            float4 b1 = *reinterpret_cast<float4*>(&Bs[kk][64 + tx * 4]);
#pragma unroll
            for (int i = 0; i < 4; i++) {
                acc[i][0] = fmaf(a[i], b0.x, acc[i][0]);
                acc[i][1] = fmaf(a[i], b0.y, acc[i][1]);
                acc[i][2] = fmaf(a[i], b0.z, acc[i][2]);
                acc[i][3] = fmaf(a[i], b0.w, acc[i][3]);
                acc[i][4] = fmaf(a[i], b1.x, acc[i][4]);
                acc[i][5] = fmaf(a[i], b1.y, acc[i][5]);
                acc[i][6] = fmaf(a[i], b1.z, acc[i][6]);
                acc[i][7] = fmaf(a[i], b1.w, acc[i][7]);
            }
        }
        __syncthreads();
    }

    // epilogue
#pragma unroll
    for (int i = 0; i < 4; i++) {
        int node = r0 + ty * 4 + i;
#pragma unroll
        for (int j = 0; j < 8; j++) {
            int col = (j < 4) ? (tx * 4 + j) : (64 + tx * 4 + (j - 4));
            int idx = node * DLAT + col;
            float v = acc[i][j];
            if (which == 0) {
                g_zd[idx] = v;
                out[OUT_NN + idx] = v;
            } else if (which == 1) {
                out[OUT_NN + OUT_NL + idx] = v;
                g_ig[idx] = 1.f / (v + 1e-16f);
            } else {
                out[OUT_NN + 2 * OUT_NL + idx] = v;
                g_id[idx] = 1.f / (v + 1e-16f);
            }
        }
    }
}

// ---------------- K2b: build U, V (bf16) and c, d ---------------------------
__global__ void prep_kernel(const float* __restrict__ pb,
                            const float* __restrict__ pwg,
                            const float* __restrict__ pwd) {
    int i = blockIdx.x;
    int k = threadIdx.x;   // 128
    float zd = g_zd[i * DLAT + k];
    float ig = g_ig[i * DLAT + k];
    float id = g_id[i * DLAT + k];
    float z2 = zd * zd;
    float bias = *pb, wg = *pwg, wd = *pwd;
    const float n = 8192.0f;

    g_U[i * KDIM + 0   + k] = __float2bfloat16_rn(-wg * n * ig);
    g_U[i * KDIM + 128 + k] = __float2bfloat16_rn(2.f * wg * n * zd * ig);
    g_U[i * KDIM + 256 + k] = __float2bfloat16_rn(-wd * n * z2);
    g_U[i * KDIM + 384 + k] = __float2bfloat16_rn(2.f * wd * n * zd);

    g_V[i * KDIM + 0   + k] = __float2bfloat16_rn(z2);
    g_V[i * KDIM + 128 + k] = __float2bfloat16_rn(zd);
    g_V[i * KDIM + 256 + k] = __float2bfloat16_rn(id);
    g_V[i * KDIM + 384 + k] = __float2bfloat16_rn(zd * id);

    float a = z2 * ig, b = z2 * id;
#pragma unroll
    for (int o = 16; o > 0; o >>= 1) {
        a += __shfl_down_sync(0xffffffffu, a, o);
        b += __shfl_down_sync(0xffffffffu, b, o);
    }
    __shared__ float sa[4], sb[4];
    if ((k & 31) == 0) { sa[k >> 5] = a; sb[k >> 5] = b; }
    __syncthreads();
    if (k == 0) {
        float A = sa[0] + sa[1] + sa[2] + sa[3];
        float Bv = sb[0] + sb[1] + sb[2] + sb[3];
        g_c[i] = bias - wg * n * A;
        g_d[i] = -wd * n * Bv;
    }
}

// ---------------- K3: 8192x8192x512 bf16 GEMM + sigmoid epilogue ------------
__device__ __forceinline__ void ldsm_x4(uint32_t& r0, uint32_t& r1,
                                        uint32_t& r2, uint32_t& r3, uint32_t addr) {
    asm volatile("ldmatrix.sync.aligned.m8n8.x4.shared.b16 {%0,%1,%2,%3}, [%4];\n"
                 : "=r"(r0), "=r"(r1), "=r"(r2), "=r"(r3) : "r"(addr));
}
__device__ __forceinline__ void ldsm_x2(uint32_t& r0, uint32_t& r1, uint32_t addr) {
    asm volatile("ldmatrix.sync.aligned.m8n8.x2.shared.b16 {%0,%1}, [%2];\n"
                 : "=r"(r0), "=r"(r1) : "r"(addr));
}
__device__ __forceinline__ void mma_bf16(float& c0, float& c1, float& c2, float& c3,
                                         uint32_t a0, uint32_t a1, uint32_t a2, uint32_t a3,
                                         uint32_t b0, uint32_t b1) {
    asm volatile("mma.sync.aligned.m16n8k16.row.col.f32.bf16.bf16.f32 "
                 "{%0,%1,%2,%3}, {%4,%5,%6,%7}, {%8,%9}, {%0,%1,%2,%3};\n"
                 : "+f"(c0), "+f"(c1), "+f"(c2), "+f"(c3)
                 : "r"(a0), "r"(a1), "r"(a2), "r"(a3), "r"(b0), "r"(b1));
}

// exact (cancellation-free) recompute for near-diagonal elements
__device__ __noinline__ float exact_x(int i, int j, float bias, float wg, float wd) {
    const float* zi = &g_zd[i * DLAT];
    const float* zj = &g_zd[j * DLAT];
    const float* gi = &g_ig[i * DLAT];
    const float* dj = &g_id[j * DLAT];
    float s = 0.f;
    for (int k = 0; k < DLAT; k++) {
        float d = zi[k] - zj[k];
        s = fmaf(d * d, wg * gi[k] + wd * dj[k], s);
    }
    return bias - 8192.0f * s;
}

// sigmoid with exact-underflow fast path: for x < -88, expf(-x) = +inf in
// fp32 => sigmoid is exactly 0.0f, matching the fp32 reference bit-for-bit.
__device__ __forceinline__ float fast_sigmoid(float x) {
    if (x < -88.f) return 0.f;
    return 1.f / (1.f + expf(-x));
}

#define SPAD 40   // smem row stride (elements); 20-bank row shift => conflict-free ldmatrix

__global__ __launch_bounds__(256) void pair_kernel(float* __restrict__ out,
                                                   const float* __restrict__ pb,
                                                   const float* __restrict__ pwg,
                                                   const float* __restrict__ pwd) {
    __shared__ __align__(16) __nv_bfloat16 sA[2][128][SPAD];
    __shared__ __align__(16) __nv_bfloat16 sB[2][128][SPAD];

    int tid = threadIdx.x;
    int lane = tid & 31, wid = tid >> 5;
    int warpM = wid >> 2, warpN = wid & 3;     // 2 x 4 warps, warp tile 64x32
    int i0 = blockIdx.y * 128, j0 = blockIdx.x * 128;

    float acc[4][4][4];
#pragma unroll
    for (int a = 0; a < 4; a++)
#pragma unroll
        for (int b = 0; b < 4; b++)
#pragma unroll
            for (int c = 0; c < 4; c++) acc[a][b][c] = 0.f;

    // global-load / smem-store lane mapping (2 uint4 per operand per thread)
    int lrow[2], lq[2];
#pragma unroll
    for (int it = 0; it < 2; it++) {
        int linear = tid + it * 256;
        lrow[it] = linear >> 2;
        lq[it] = linear & 3;
    }

    // ldmatrix lane offsets
    int a_m = (lane & 7) + ((lane >> 3) & 1) * 8;   // + warpM*64 + mf*16
    int a_k = ((lane >> 4) & 1) * 8;                // + ks*16
    int l16 = lane & 15;
    int b_n = l16 & 7;                              // + warpN*32 + nf*8
    int b_k = (l16 >> 3) * 8;                       // + ks*16

    uint4 ra[2], rb[2];

    // prologue: chunk 0
#pragma unroll
    for (int it = 0; it < 2; it++) {
        ra[it] = *reinterpret_cast<const uint4*>(&g_U[(i0 + lrow[it]) * KDIM + lq[it] * 8]);
        rb[it] = *reinterpret_cast<const uint4*>(&g_V[(j0 + lrow[it]) * KDIM + lq[it] * 8]);
    }
#pragma unroll
    for (int it = 0; it < 2; it++) {
        __nv_bfloat16* pa = &sA[0][lrow[it]][lq[it] * 8];
        __nv_bfloat16* pbm = &sB[0][lrow[it]][lq[it] * 8];
        *reinterpret_cast<uint2*>(pa)      = make_uint2(ra[it].x, ra[it].y);
        *reinterpret_cast<uint2*>(pa + 4)  = make_uint2(ra[it].z, ra[it].w);
        *reinterpret_cast<uint2*>(pbm)     = make_uint2(rb[it].x, rb[it].y);
        *reinterpret_cast<uint2*>(pbm + 4) = make_uint2(rb[it].z, rb[it].w);
    }
    __syncthreads();

    const int NCHUNK = KDIM / 32;   // 16
#pragma unroll 1
    for (int kc = 0; kc < NCHUNK; kc++) {
        if (kc < NCHUNK - 1) {
            int koff = (kc + 1) * 32;
#pragma unroll
            for (int it = 0; it < 2; it++) {
                ra[it] = *reinterpret_cast<const uint4*>(
                    &g_U[(i0 + lrow[it]) * KDIM + koff + lq[it] * 8]);
                rb[it] = *reinterpret_cast<const uint4*>(
                    &g_V[(j0 + lrow[it]) * KDIM + koff + lq[it] * 8]);
            }
        }

        // compute on buffer kc&1
        {
            int buf = kc & 1;
            uint32_t baseA = (uint32_t)__cvta_generic_to_shared(&sA[buf][0][0]);
            uint32_t baseB = (uint32_t)__cvta_generic_to_shared(&sB[buf][0][0]);
#pragma unroll
            for (int ks = 0; ks < 2; ks++) {
                uint32_t af[4][4], bf[4][2];
#pragma unroll
                for (int mf = 0; mf < 4; mf++) {
                    int mm = warpM * 64 + mf * 16 + a_m;
                    int kk = ks * 16 + a_k;
                    ldsm_x4(af[mf][0], af[mf][1], af[mf][2], af[mf][3],
                            baseA + (uint32_t)(mm * SPAD + kk) * 2u);
                }
#pragma unroll
                for (int nf = 0; nf < 4; nf++) {
                    int nn = warpN * 32 + nf * 8 + b_n;
                    int kk = ks * 16 + b_k;
                    ldsm_x2(bf[nf][0], bf[nf][1],
                            baseB + (uint32_t)(nn * SPAD + kk) * 2u);
                }
#pragma unroll
                for (int mf = 0; mf < 4; mf++)
#pragma unroll
                    for (int nf = 0; nf < 4; nf++)
                        mma_bf16(acc[mf][nf][0], acc[mf][nf][1], acc[mf][nf][2], acc[mf][nf][3],
                                 af[mf][0], af[mf][1], af[mf][2], af[mf][3],
                                 bf[nf][0], bf[nf][1]);
            }
        }

        if (kc < NCHUNK - 1) {
            int buf = (kc + 1) & 1;
#pragma unroll
            for (int it = 0; it < 2; it++) {
                __nv_bfloat16* pa = &sA[buf][lrow[it]][lq[it] * 8];
                __nv_bfloat16* pbm = &sB[buf][lrow[it]][lq[it] * 8];
                *reinterpret_cast<uint2*>(pa)      = make_uint2(ra[it].x, ra[it].y);
                *reinterpret_cast<uint2*>(pa + 4)  = make_uint2(ra[it].z, ra[it].w);
                *reinterpret_cast<uint2*>(pbm)     = make_uint2(rb[it].x, rb[it].y);
                *reinterpret_cast<uint2*>(pbm + 4) = make_uint2(rb[it].z, rb[it].w);
            }
        }
        __syncthreads();
    }

    // epilogue
    float bias = *pb, wg = *pwg, wd = *pwd;
    int lr = lane >> 2, lc = (lane & 3) * 2;
#pragma unroll
    for (int mf = 0; mf < 4; mf++) {
#pragma unroll
        for (int nf = 0; nf < 4; nf++) {
            int i1 = i0 + warpM * 64 + mf * 16 + lr;
            int j = j0 + warpN * 32 + nf * 8 + lc;
#pragma unroll
            for (int half = 0; half < 2; half++) {
                int i = i1 + half * 8;
                float ci = g_c[i];
                float x0 = acc[mf][nf][half * 2 + 0] + ci + g_d[j];
                float x1 = acc[mf][nf][half * 2 + 1] + ci + g_d[j + 1];
                if (x0 > -300.f) x0 = exact_x(i, j, bias, wg, wd);
                if (x1 > -300.f) x1 = exact_x(i, j + 1, bias, wg, wd);
                float2 r;
                r.x = fast_sigmoid(x0);
                r.y = fast_sigmoid(x1);
                *reinterpret_cast<float2*>(&out[(size_t)i * NNODE + j]) = r;
            }
        }
    }
}

// ---------------- launch -----------------------------------------------------
extern "C" void kernel_launch(void* const* d_in, const int* in_sizes, int n_in,
                              void* d_out, int out_size) {
    const float* z     = (const float*)d_in[0];
    const float* gamma = (const float*)d_in[1];
    const float* delta = (const float*)d_in[2];
    const float* Wz    = (const float*)d_in[3];
    const float* Wg    = (const float*)d_in[4];
    const float* Wd    = (const float*)d_in[5];
    const float* pb    = (const float*)d_in[6];
    const float* pwg   = (const float*)d_in[7];
    const float* pwd   = (const float*)d_in[8];
    float* out = (float*)d_out;

    softmax_cols<<<384, 128>>>(Wz, Wg, Wd);
    gemm_small<<<dim3(NNODE / 64, 3), 256>>>(z, gamma, delta, out);
    prep_kernel<<<NNODE, 128>>>(pb, pwg, pwd);
    pair_kernel<<<dim3(NNODE / 128, NNODE / 128), 256>>>(out, pb, pwg, pwd);
}

// round 5
// speedup vs baseline: 5.4847x; 5.4782x over previous
#include <cuda_runtime.h>
#include <cuda_bf16.h>
#include <cstdint>
#include <math.h>

#define NNODE 8192
#define DIN   512
#define DLAT  128
#define NSLOT 30            // split slots per latent k
#define KSPL  (DLAT * NSLOT)   // 3840

static const int OUT_NN = NNODE * NNODE;           // 67108864
static const int OUT_NL = NNODE * DLAT;            // 1048576

// ---------------- scratch (device globals; no allocation allowed) ----------
__device__ float g_T[3][DIN][DLAT];                // softmaxed transforms
__device__ float g_zd[NNODE * DLAT];
__device__ float g_ig[NNODE * DLAT];               // 1/(gd+SMALL)
__device__ float g_id[NNODE * DLAT];               // 1/(dd+SMALL)
__device__ __nv_bfloat16 g_U[(size_t)NNODE * KSPL];  // split-U (63 MB)
__device__ __nv_bfloat16 g_V[(size_t)NNODE * KSPL];  // split-V (63 MB)

// ---------------- K1: column softmax of the three W matrices ---------------
__global__ void softmax_cols(const float* __restrict__ Wz,
                             const float* __restrict__ Wg,
                             const float* __restrict__ Wd) {
    int mat = blockIdx.x >> 7;        // 0..2
    int col = blockIdx.x & 127;
    const float* W = (mat == 0) ? Wz : (mat == 1) ? Wg : Wd;
    int t = threadIdx.x;              // 128 threads
    __shared__ float red[128];

    float v[4];
#pragma unroll
    for (int r = 0; r < 4; r++) v[r] = W[(t + r * 128) * DLAT + col];

    float m = fmaxf(fmaxf(v[0], v[1]), fmaxf(v[2], v[3]));
    red[t] = m; __syncthreads();
    for (int s = 64; s > 0; s >>= 1) {
        if (t < s) red[t] = fmaxf(red[t], red[t + s]);
        __syncthreads();
    }
    m = red[0]; __syncthreads();

    float e[4], sum = 0.f;
#pragma unroll
    for (int r = 0; r < 4; r++) { e[r] = expf(v[r] - m); sum += e[r]; }
    red[t] = sum; __syncthreads();
    for (int s = 64; s > 0; s >>= 1) {
        if (t < s) red[t] += red[t + s];
        __syncthreads();
    }
    float inv = 1.f / red[0];
#pragma unroll
    for (int r = 0; r < 4; r++) g_T[mat][t + r * 128][col] = e[r] * inv;
}

// ---------------- K2a: zd / gd / dd GEMMs (fp32 SIMT) ----------------------
__global__ __launch_bounds__(256) void gemm_small(const float* __restrict__ z,
                                                  const float* __restrict__ gamma,
                                                  const float* __restrict__ delta,
                                                  float* __restrict__ out) {
    __shared__ float As[32][65];      // [k][m] transposed
    __shared__ float Bs[32][128];

    int which = blockIdx.y;
    const float* A = (which == 0) ? z : (which == 1) ? gamma : delta;
    const float* B = &g_T[which][0][0];
    int r0 = blockIdx.x * 64;

    int tid = threadIdx.x;
    int ty = tid >> 4, tx = tid & 15;

    float acc[4][8];
#pragma unroll
    for (int i = 0; i < 4; i++)
#pragma unroll
        for (int j = 0; j < 8; j++) acc[i][j] = 0.f;

    for (int kc = 0; kc < DIN / 32; kc++) {
#pragma unroll
        for (int it = 0; it < 2; it++) {
            int linear = tid + it * 256;          // 0..511
            int arow = linear >> 3, ac4 = linear & 7;
            float4 va = *reinterpret_cast<const float4*>(
                &A[(r0 + arow) * DIN + kc * 32 + ac4 * 4]);
            As[ac4 * 4 + 0][arow] = va.x;
            As[ac4 * 4 + 1][arow] = va.y;
            As[ac4 * 4 + 2][arow] = va.z;
            As[ac4 * 4 + 3][arow] = va.w;
        }
#pragma unroll
        for (int it = 0; it < 4; it++) {
            int linear = tid + it * 256;          // 0..1023
            int brow = linear >> 5, bc4 = linear & 31;
            *reinterpret_cast<float4*>(&Bs[brow][bc4 * 4]) =
                *reinterpret_cast<const float4*>(&B[(kc * 32 + brow) * DLAT + bc4 * 4]);
        }
        __syncthreads();

#pragma unroll
        for (int kk = 0; kk < 32; kk++) {
            float a[4];
#pragma unroll
            for (int i = 0; i < 4; i++) a[i] = As[kk][ty * 4 + i];
            float4 b0 = *reinterpret_cast<float4*>(&Bs[kk][tx * 4]);
            float4 b1 = *reinterpret_cast<float4*>(&Bs[kk][64 + tx * 4]);
#pragma unroll
            for (int i = 0; i < 4; i++) {
                acc[i][0] = fmaf(a[i], b0.x, acc[i][0]);
                acc[i][1] = fmaf(a[i], b0.y, acc[i][1]);
                acc[i][2] = fmaf(a[i], b0.z, acc[i][2]);
                acc[i][3] = fmaf(a[i], b0.w, acc[i][3]);
                acc[i][4] = fmaf(a[i], b1.x, acc[i][4]);
                acc[i][5] = fmaf(a[i], b1.y, acc[i][5]);
                acc[i][6] = fmaf(a[i], b1.z, acc[i][6]);
                acc[i][7] = fmaf(a[i], b1.w, acc[i][7]);
            }
        }
        __syncthreads();
    }

#pragma unroll
    for (int i = 0; i < 4; i++) {
        int node = r0 + ty * 4 + i;
#pragma unroll
        for (int j = 0; j < 8; j++) {
            int col = (j < 4) ? (tx * 4 + j) : (64 + tx * 4 + (j - 4));
            int idx = node * DLAT + col;
            float v = acc[i][j];
            if (which == 0) {
                g_zd[idx] = v;
                out[OUT_NN + idx] = v;
            } else if (which == 1) {
                out[OUT_NN + OUT_NL + idx] = v;
                g_ig[idx] = 1.f / (v + 1e-16f);
            } else {
                out[OUT_NN + 2 * OUT_NL + idx] = v;
                g_id[idx] = 1.f / (v + 1e-16f);
            }
        }
    }
}

// ---------------- K2b: build telescoped split U, V (bf16) -------------------
// Per latent k, 30 slots; each k-cluster sums EXACTLY to
//   -n (zd_i - zd_j)^2 (wg*ig_i + wd*id_j)   (always <= 0, small for near pairs)
// so the fp32 mma accumulator tracks the partial x, never a large cancelling sum.
// Slots:  [0..2]  u1{h,m,l}        v = 1          (u1 = -wgn*ig*z2)
//         [3..8]  P6(u2 , v2)                     (u2 = 2*wgn*ig*zd, v2 = zd)
//         [9..14] P6(u3 , v3)                     (u3 = -wgn*ig,     v3 = z2)
//         [15..20]P6(u4 , v4)                     (u4 = -z2,  v4 = wdn*id)
//         [21..26]P6(u5 , v5)                     (u5 = 2*zd, v5 = wdn*zd*id)
//         [27..29]u = -1            v6{h,m,l}     (v6 = wdn*z2*id)
// P6 pairings: (h,h)(h,m)(m,h)(h,l)(l,h)(m,m)  — keeps all terms >= 2^-16|uv|.
__device__ __forceinline__ void split3(float x, float& h, float& m, float& l) {
    h = __bfloat162float(__float2bfloat16_rn(x));
    float r = x - h;
    m = __bfloat162float(__float2bfloat16_rn(r));
    l = r - m;
}

__global__ __launch_bounds__(128) void prep_split(const float* __restrict__ pwg,
                                                  const float* __restrict__ pwd) {
    int i = blockIdx.x;
    int k = threadIdx.x;          // 0..127
    float zd = g_zd[i * DLAT + k];
    float ig = g_ig[i * DLAT + k];
    float id = g_id[i * DLAT + k];
    float z2 = zd * zd;
    float wgn = (*pwg) * 8192.0f;
    float wdn = (*pwd) * 8192.0f;

    float u1 = -(wgn * ig * z2);
    float u2 = 2.f * wgn * ig * zd;
    float u3 = -(wgn * ig);
    float u4 = -z2;
    float u5 = 2.f * zd;
    float v2 = zd;
    float v3 = z2;
    float v4 = wdn * id;
    float v5 = wdn * zd * id;
    float v6 = wdn * z2 * id;

    float us[NSLOT], vs[NSLOT];
    float h, m, l, hv, mv, lv;

    split3(u1, h, m, l);
    us[0] = h; us[1] = m; us[2] = l;
    vs[0] = 1.f; vs[1] = 1.f; vs[2] = 1.f;

#define P6(base, U, V)                                            \
    split3(U, h, m, l); split3(V, hv, mv, lv);                    \
    us[base+0]=h; vs[base+0]=hv;  us[base+1]=h; vs[base+1]=mv;    \
    us[base+2]=m; vs[base+2]=hv;  us[base+3]=h; vs[base+3]=lv;    \
    us[base+4]=l; vs[base+4]=hv;  us[base+5]=m; vs[base+5]=mv;

    P6(3,  u2, v2)
    P6(9,  u3, v3)
    P6(15, u4, v4)
    P6(21, u5, v5)
#undef P6

    split3(v6, hv, mv, lv);
    us[27] = -1.f; us[28] = -1.f; us[29] = -1.f;
    vs[27] = hv;   vs[28] = mv;   vs[29] = lv;

    size_t base = (size_t)i * KSPL + (size_t)k * NSLOT;
#pragma unroll
    for (int s = 0; s < NSLOT; s++) {
        g_U[base + s] = __float2bfloat16_rn(us[s]);
        g_V[base + s] = __float2bfloat16_rn(vs[s]);
    }
}

// ---------------- K3: 8192x8192x3840 bf16 GEMM + sigmoid epilogue -----------
__device__ __forceinline__ void ldsm_x4(uint32_t& r0, uint32_t& r1,
                                        uint32_t& r2, uint32_t& r3, uint32_t addr) {
    asm volatile("ldmatrix.sync.aligned.m8n8.x4.shared.b16 {%0,%1,%2,%3}, [%4];\n"
                 : "=r"(r0), "=r"(r1), "=r"(r2), "=r"(r3) : "r"(addr));
}
__device__ __forceinline__ void ldsm_x2(uint32_t& r0, uint32_t& r1, uint32_t addr) {
    asm volatile("ldmatrix.sync.aligned.m8n8.x2.shared.b16 {%0,%1}, [%2];\n"
                 : "=r"(r0), "=r"(r1) : "r"(addr));
}
__device__ __forceinline__ void mma_bf16(float& c0, float& c1, float& c2, float& c3,
                                         uint32_t a0, uint32_t a1, uint32_t a2, uint32_t a3,
                                         uint32_t b0, uint32_t b1) {
    asm volatile("mma.sync.aligned.m16n8k16.row.col.f32.bf16.bf16.f32 "
                 "{%0,%1,%2,%3}, {%4,%5,%6,%7}, {%8,%9}, {%0,%1,%2,%3};\n"
                 : "+f"(c0), "+f"(c1), "+f"(c2), "+f"(c3)
                 : "r"(a0), "r"(a1), "r"(a2), "r"(a3), "r"(b0), "r"(b1));
}

// sigmoid; for x < -88, expf fp32-underflows => exactly 0.0f like the reference
__device__ __forceinline__ float fast_sigmoid(float x) {
    if (x < -88.f) return 0.f;
    return 1.f / (1.f + expf(-x));
}

#define SPAD 40   // smem row stride (elements)

__global__ __launch_bounds__(256) void pair_kernel(float* __restrict__ out,
                                                   const float* __restrict__ pb) {
    __shared__ __align__(16) __nv_bfloat16 sA[2][128][SPAD];
    __shared__ __align__(16) __nv_bfloat16 sB[2][128][SPAD];

    int tid = threadIdx.x;
    int lane = tid & 31, wid = tid >> 5;
    int warpM = wid >> 2, warpN = wid & 3;     // 2 x 4 warps, warp tile 64x32

    // 8-row block swizzle for L2 reuse of U/V tiles
    int flat = blockIdx.y * 64 + blockIdx.x;   // 0..4095
    int grp = flat >> 9;                       // / (8*64): 0..7
    int rem = flat & 511;
    int brow = grp * 8 + (rem & 7);
    int bcol = rem >> 3;
    int i0 = brow * 128, j0 = bcol * 128;

    float acc[4][4][4];
#pragma unroll
    for (int a = 0; a < 4; a++)
#pragma unroll
        for (int b = 0; b < 4; b++)
#pragma unroll
            for (int c = 0; c < 4; c++) acc[a][b][c] = 0.f;

    int lrow[2], lq[2];
#pragma unroll
    for (int it = 0; it < 2; it++) {
        int linear = tid + it * 256;
        lrow[it] = linear >> 2;
        lq[it] = linear & 3;
    }

    int a_m = (lane & 7) + ((lane >> 3) & 1) * 8;
    int a_k = ((lane >> 4) & 1) * 8;
    int l16 = lane & 15;
    int b_n = l16 & 7;
    int b_k = (l16 >> 3) * 8;

    uint4 ra[2], rb[2];

    // prologue: chunk 0
#pragma unroll
    for (int it = 0; it < 2; it++) {
        ra[it] = *reinterpret_cast<const uint4*>(&g_U[(size_t)(i0 + lrow[it]) * KSPL + lq[it] * 8]);
        rb[it] = *reinterpret_cast<const uint4*>(&g_V[(size_t)(j0 + lrow[it]) * KSPL + lq[it] * 8]);
    }
#pragma unroll
    for (int it = 0; it < 2; it++) {
        __nv_bfloat16* pa = &sA[0][lrow[it]][lq[it] * 8];
        __nv_bfloat16* pbm = &sB[0][lrow[it]][lq[it] * 8];
        *reinterpret_cast<uint2*>(pa)      = make_uint2(ra[it].x, ra[it].y);
        *reinterpret_cast<uint2*>(pa + 4)  = make_uint2(ra[it].z, ra[it].w);
        *reinterpret_cast<uint2*>(pbm)     = make_uint2(rb[it].x, rb[it].y);
        *reinterpret_cast<uint2*>(pbm + 4) = make_uint2(rb[it].z, rb[it].w);
    }
    __syncthreads();

    const int NCHUNK = KSPL / 32;   // 120
#pragma unroll 1
    for (int kc = 0; kc < NCHUNK; kc++) {
        if (kc < NCHUNK - 1) {
            int koff = (kc + 1) * 32;
#pragma unroll
            for (int it = 0; it < 2; it++) {
                ra[it] = *reinterpret_cast<const uint4*>(
                    &g_U[(size_t)(i0 + lrow[it]) * KSPL + koff + lq[it] * 8]);
                rb[it] = *reinterpret_cast<const uint4*>(
                    &g_V[(size_t)(j0 + lrow[it]) * KSPL + koff + lq[it] * 8]);
            }
        }

        {
            int buf = kc & 1;
            uint32_t baseA = (uint32_t)__cvta_generic_to_shared(&sA[buf][0][0]);
            uint32_t baseB = (uint32_t)__cvta_generic_to_shared(&sB[buf][0][0]);
#pragma unroll
            for (int ks = 0; ks < 2; ks++) {
                uint32_t af[4][4], bf[4][2];
#pragma unroll
                for (int mf = 0; mf < 4; mf++) {
                    int mm = warpM * 64 + mf * 16 + a_m;
                    int kk = ks * 16 + a_k;
                    ldsm_x4(af[mf][0], af[mf][1], af[mf][2], af[mf][3],
                            baseA + (uint32_t)(mm * SPAD + kk) * 2u);
                }
#pragma unroll
                for (int nf = 0; nf < 4; nf++) {
                    int nn = warpN * 32 + nf * 8 + b_n;
                    int kk = ks * 16 + b_k;
                    ldsm_x2(bf[nf][0], bf[nf][1],
                            baseB + (uint32_t)(nn * SPAD + kk) * 2u);
                }
#pragma unroll
                for (int mf = 0; mf < 4; mf++)
#pragma unroll
                    for (int nf = 0; nf < 4; nf++)
                        mma_bf16(acc[mf][nf][0], acc[mf][nf][1], acc[mf][nf][2], acc[mf][nf][3],
                                 af[mf][0], af[mf][1], af[mf][2], af[mf][3],
                                 bf[nf][0], bf[nf][1]);
            }
        }

        if (kc < NCHUNK - 1) {
            int buf = (kc + 1) & 1;
#pragma unroll
            for (int it = 0; it < 2; it++) {
                __nv_bfloat16* pa = &sA[buf][lrow[it]][lq[it] * 8];
                __nv_bfloat16* pbm = &sB[buf][lrow[it]][lq[it] * 8];
                *reinterpret_cast<uint2*>(pa)      = make_uint2(ra[it].x, ra[it].y);
                *reinterpret_cast<uint2*>(pa + 4)  = make_uint2(ra[it].z, ra[it].w);
                *reinterpret_cast<uint2*>(pbm)     = make_uint2(rb[it].x, rb[it].y);
                *reinterpret_cast<uint2*>(pbm + 4) = make_uint2(rb[it].z, rb[it].w);
            }
        }
        __syncthreads();
    }

    // epilogue: x = acc + bias ; sigmoid with exact-underflow fast path
    float bias = *pb;
    int lr = lane >> 2, lc = (lane & 3) * 2;
#pragma unroll
    for (int mf = 0; mf < 4; mf++) {
#pragma unroll
        for (int nf = 0; nf < 4; nf++) {
            int i1 = i0 + warpM * 64 + mf * 16 + lr;
            int j = j0 + warpN * 32 + nf * 8 + lc;
#pragma unroll
            for (int half = 0; half < 2; half++) {
                int i = i1 + half * 8;
                float x0 = acc[mf][nf][half * 2 + 0] + bias;
                float x1 = acc[mf][nf][half * 2 + 1] + bias;
                float2 r;
                r.x = fast_sigmoid(x0);
                r.y = fast_sigmoid(x1);
                *reinterpret_cast<float2*>(&out[(size_t)i * NNODE + j]) = r;
            }
        }
    }
}

// ---------------- launch -----------------------------------------------------
extern "C" void kernel_launch(void* const* d_in, const int* in_sizes, int n_in,
                              void* d_out, int out_size) {
    const float* z     = (const float*)d_in[0];
    const float* gamma = (const float*)d_in[1];
    const float* delta = (const float*)d_in[2];
    const float* Wz    = (const float*)d_in[3];
    const float* Wg    = (const float*)d_in[4];
    const float* Wd    = (const float*)d_in[5];
    const float* pb    = (const float*)d_in[6];
    const float* pwg   = (const float*)d_in[7];
    const float* pwd   = (const float*)d_in[8];
    float* out = (float*)d_out;

    softmax_cols<<<384, 128>>>(Wz, Wg, Wd);
    gemm_small<<<dim3(NNODE / 64, 3), 256>>>(z, gamma, delta, out);
    prep_split<<<NNODE, 128>>>(pwg, pwd);
    pair_kernel<<<dim3(NNODE / 128, NNODE / 128), 256>>>(out, pb);
}

// round 6
// speedup vs baseline: 10.9843x; 2.0027x over previous
#include <cuda_runtime.h>
#include <cuda_fp16.h>
#include <cstdint>
#include <math.h>

#define NNODE 8192
#define DIN   512
#define DLAT  128
#define NSLOT 16               // fp16 split slots per latent k
#define KSPL  (DLAT * NSLOT)   // 2048

static const int OUT_NN = NNODE * NNODE;           // 67108864
static const int OUT_NL = NNODE * DLAT;            // 1048576

// ---------------- scratch (device globals; no allocation allowed) ----------
__device__ float g_T[3][DIN][DLAT];                // softmaxed transforms
__device__ float g_zd[NNODE * DLAT];
__device__ float g_ig[NNODE * DLAT];               // 1/(gd+SMALL)
__device__ float g_id[NNODE * DLAT];               // 1/(dd+SMALL)
__device__ __half g_U[(size_t)NNODE * KSPL];       // split-U (32 MB)
__device__ __half g_V[(size_t)NNODE * KSPL];       // split-V (32 MB)

// ---------------- K1: column softmax of the three W matrices ---------------
__global__ void softmax_cols(const float* __restrict__ Wz,
                             const float* __restrict__ Wg,
                             const float* __restrict__ Wd) {
    int mat = blockIdx.x >> 7;        // 0..2
    int col = blockIdx.x & 127;
    const float* W = (mat == 0) ? Wz : (mat == 1) ? Wg : Wd;
    int t = threadIdx.x;              // 128 threads
    __shared__ float red[128];

    float v[4];
#pragma unroll
    for (int r = 0; r < 4; r++) v[r] = W[(t + r * 128) * DLAT + col];

    float m = fmaxf(fmaxf(v[0], v[1]), fmaxf(v[2], v[3]));
    red[t] = m; __syncthreads();
    for (int s = 64; s > 0; s >>= 1) {
        if (t < s) red[t] = fmaxf(red[t], red[t + s]);
        __syncthreads();
    }
    m = red[0]; __syncthreads();

    float e[4], sum = 0.f;
#pragma unroll
    for (int r = 0; r < 4; r++) { e[r] = expf(v[r] - m); sum += e[r]; }
    red[t] = sum; __syncthreads();
    for (int s = 64; s > 0; s >>= 1) {
        if (t < s) red[t] += red[t + s];
        __syncthreads();
    }
    float inv = 1.f / red[0];
#pragma unroll
    for (int r = 0; r < 4; r++) g_T[mat][t + r * 128][col] = e[r] * inv;
}

// ---------------- K2a: zd / gd / dd GEMMs (fp32 SIMT) ----------------------
__global__ __launch_bounds__(256) void gemm_small(const float* __restrict__ z,
                                                  const float* __restrict__ gamma,
                                                  const float* __restrict__ delta,
                                                  float* __restrict__ out) {
    __shared__ float As[32][65];      // [k][m] transposed
    __shared__ float Bs[32][128];

    int which = blockIdx.y;
    const float* A = (which == 0) ? z : (which == 1) ? gamma : delta;
    const float* B = &g_T[which][0][0];
    int r0 = blockIdx.x * 64;

    int tid = threadIdx.x;
    int ty = tid >> 4, tx = tid & 15;

    float acc[4][8];
#pragma unroll
    for (int i = 0; i < 4; i++)
#pragma unroll
        for (int j = 0; j < 8; j++) acc[i][j] = 0.f;

    for (int kc = 0; kc < DIN / 32; kc++) {
#pragma unroll
        for (int it = 0; it < 2; it++) {
            int linear = tid + it * 256;          // 0..511
            int arow = linear >> 3, ac4 = linear & 7;
            float4 va = *reinterpret_cast<const float4*>(
                &A[(r0 + arow) * DIN + kc * 32 + ac4 * 4]);
            As[ac4 * 4 + 0][arow] = va.x;
            As[ac4 * 4 + 1][arow] = va.y;
            As[ac4 * 4 + 2][arow] = va.z;
            As[ac4 * 4 + 3][arow] = va.w;
        }
#pragma unroll
        for (int it = 0; it < 4; it++) {
            int linear = tid + it * 256;          // 0..1023
            int brow = linear >> 5, bc4 = linear & 31;
            *reinterpret_cast<float4*>(&Bs[brow][bc4 * 4]) =
                *reinterpret_cast<const float4*>(&B[(kc * 32 + brow) * DLAT + bc4 * 4]);
        }
        __syncthreads();

#pragma unroll
        for (int kk = 0; kk < 32; kk++) {
            float a[4];
#pragma unroll
            for (int i = 0; i < 4; i++) a[i] = As[kk][ty * 4 + i];
            float4 b0 = *reinterpret_cast<float4*>(&Bs[kk][tx * 4]);
            float4 b1 = *reinterpret_cast<float4*>(&Bs[kk][64 + tx * 4]);
#pragma unroll
            for (int i = 0; i < 4; i++) {
                acc[i][0] = fmaf(a[i], b0.x, acc[i][0]);
                acc[i][1] = fmaf(a[i], b0.y, acc[i][1]);
                acc[i][2] = fmaf(a[i], b0.z, acc[i][2]);
                acc[i][3] = fmaf(a[i], b0.w, acc[i][3]);
                acc[i][4] = fmaf(a[i], b1.x, acc[i][4]);
                acc[i][5] = fmaf(a[i], b1.y, acc[i][5]);
                acc[i][6] = fmaf(a[i], b1.z, acc[i][6]);
                acc[i][7] = fmaf(a[i], b1.w, acc[i][7]);
            }
        }
        __syncthreads();
    }

#pragma unroll
    for (int i = 0; i < 4; i++) {
        int node = r0 + ty * 4 + i;
#pragma unroll
        for (int j = 0; j < 8; j++) {
            int col = (j < 4) ? (tx * 4 + j) : (64 + tx * 4 + (j - 4));
            int idx = node * DLAT + col;
            float v = acc[i][j];
            if (which == 0) {
                g_zd[idx] = v;
                out[OUT_NN + idx] = v;
            } else if (which == 1) {
                out[OUT_NN + OUT_NL + idx] = v;
                g_ig[idx] = 1.f / (v + 1e-16f);
            } else {
                out[OUT_NN + 2 * OUT_NL + idx] = v;
                g_id[idx] = 1.f / (v + 1e-16f);
            }
        }
    }
}

// ---------------- K2b: build telescoped fp16-split U, V ---------------------
// Per latent k, 16 slots; the k-cluster (one m16n8k16 instruction) sums to
//   -n (zd_i - zd_j)^2 (wg*ig_i + wd*id_j)  + O(2^-22) residual
// so the fp32 mma accumulator tracks the partial x directly.
// fp16 2-way split (h, l = x-h) with pairings (hh, h*l, l*h); cross terms are
// stored pre-shifted by 2^+-8 so every significant operand is a NORMAL fp16.
// Per-group power-of-2 scale balancing (su*sv = 1) centers dynamic ranges.
__device__ __forceinline__ void split2(float x, float& h, float& l) {
    h = __half2float(__float2half_rn(x));
    l = x - h;
}

__global__ __launch_bounds__(128) void prep_split(const float* __restrict__ pwg,
                                                  const float* __restrict__ pwd) {
    int i = blockIdx.x;
    int k = threadIdx.x;          // 0..127
    float zd = g_zd[i * DLAT + k];
    float ig = g_ig[i * DLAT + k];
    float id = g_id[i * DLAT + k];
    float z2 = zd * zd;
    float wgn = (*pwg) * 8192.0f;
    float wdn = (*pwd) * 8192.0f;

    // exact-singleton terms
    float u1 = -(wgn * ig * z2);      // pairs with v=1
    float v6 = wdn * z2 * id;         // pairs with u=-1
    // bilinear groups, scale-balanced (su*sv = 1)
    float U2 = (2.f * wgn * ig * zd) * 0.03125f;  // 2^-5
    float V2 = zd * 32.f;                          // 2^5
    float U3 = -(wgn * ig) * 0.0078125f;           // 2^-7
    float V3 = z2 * 128.f;                         // 2^7
    float U4 = -z2 * 128.f;                        // 2^7
    float V4 = (wdn * id) * 0.0078125f;            // 2^-7
    float U5 = (2.f * zd) * 16.f;                  // 2^4
    float V5 = (wdn * zd * id) * 0.0625f;          // 2^-4

    const float S  = 256.f;        // 2^8
    const float SI = 0.00390625f;  // 2^-8

    float us[NSLOT], vs[NSLOT];
    float h, l;

    split2(u1, h, l);
    us[0] = h;       vs[0] = 1.f;
    us[1] = l * S;   vs[1] = SI;

#define PG(b, U, V) { float uh, ul, vh, vl; split2(U, uh, ul); split2(V, vh, vl); \
    us[(b)+0] = uh;      vs[(b)+0] = vh;       \
    us[(b)+1] = uh * SI; vs[(b)+1] = vl * S;   \
    us[(b)+2] = ul * S;  vs[(b)+2] = vh * SI; }

    PG(2,  U2, V2)
    PG(5,  U3, V3)
    PG(8,  U4, V4)
    PG(11, U5, V5)
#undef PG

    split2(v6, h, l);
    us[14] = -1.f;  vs[14] = h;
    us[15] = -SI;   vs[15] = l * S;

    __half hu[NSLOT], hv[NSLOT];
#pragma unroll
    for (int s = 0; s < NSLOT; s++) {
        hu[s] = __float2half_rn(us[s]);
        hv[s] = __float2half_rn(vs[s]);
    }
    size_t base = (size_t)i * KSPL + (size_t)k * NSLOT;
    *reinterpret_cast<uint4*>(&g_U[base])     = *reinterpret_cast<uint4*>(&hu[0]);
    *reinterpret_cast<uint4*>(&g_U[base + 8]) = *reinterpret_cast<uint4*>(&hu[8]);
    *reinterpret_cast<uint4*>(&g_V[base])     = *reinterpret_cast<uint4*>(&hv[0]);
    *reinterpret_cast<uint4*>(&g_V[base + 8]) = *reinterpret_cast<uint4*>(&hv[8]);
}

// ---------------- K3: 8192x8192x2048 fp16 GEMM + sigmoid epilogue -----------
__device__ __forceinline__ void ldsm_x4(uint32_t& r0, uint32_t& r1,
                                        uint32_t& r2, uint32_t& r3, uint32_t addr) {
    asm volatile("ldmatrix.sync.aligned.m8n8.x4.shared.b16 {%0,%1,%2,%3}, [%4];\n"
                 : "=r"(r0), "=r"(r1), "=r"(r2), "=r"(r3) : "r"(addr));
}
__device__ __forceinline__ void ldsm_x2(uint32_t& r0, uint32_t& r1, uint32_t addr) {
    asm volatile("ldmatrix.sync.aligned.m8n8.x2.shared.b16 {%0,%1}, [%2];\n"
                 : "=r"(r0), "=r"(r1) : "r"(addr));
}
__device__ __forceinline__ void mma_fp16(float& c0, float& c1, float& c2, float& c3,
                                         uint32_t a0, uint32_t a1, uint32_t a2, uint32_t a3,
                                         uint32_t b0, uint32_t b1) {
    asm volatile("mma.sync.aligned.m16n8k16.row.col.f32.f16.f16.f32 "
                 "{%0,%1,%2,%3}, {%4,%5,%6,%7}, {%8,%9}, {%0,%1,%2,%3};\n"
                 : "+f"(c0), "+f"(c1), "+f"(c2), "+f"(c3)
                 : "r"(a0), "r"(a1), "r"(a2), "r"(a3), "r"(b0), "r"(b1));
}

// sigmoid; for x < -88, expf fp32-underflows => exactly 0.0f like the reference
__device__ __forceinline__ float fast_sigmoid(float x) {
    if (x < -88.f) return 0.f;
    return 1.f / (1.f + expf(-x));
}

#define SPAD 40   // smem row stride (elements)

__global__ __launch_bounds__(256) void pair_kernel(float* __restrict__ out,
                                                   const float* __restrict__ pb) {
    __shared__ __align__(16) __half sA[2][128][SPAD];
    __shared__ __align__(16) __half sB[2][128][SPAD];

    int tid = threadIdx.x;
    int lane = tid & 31, wid = tid >> 5;
    int warpM = wid >> 2, warpN = wid & 3;     // 2 x 4 warps, warp tile 64x32

    // 8-row block swizzle for L2 reuse of U/V tiles
    int flat = blockIdx.y * 64 + blockIdx.x;   // 0..4095
    int grp = flat >> 9;                       // / (8*64): 0..7
    int rem = flat & 511;
    int brow = grp * 8 + (rem & 7);
    int bcol = rem >> 3;
    int i0 = brow * 128, j0 = bcol * 128;

    float acc[4][4][4];
#pragma unroll
    for (int a = 0; a < 4; a++)
#pragma unroll
        for (int b = 0; b < 4; b++)
#pragma unroll
            for (int c = 0; c < 4; c++) acc[a][b][c] = 0.f;

    int lrow[2], lq[2];
#pragma unroll
    for (int it = 0; it < 2; it++) {
        int linear = tid + it * 256;
        lrow[it] = linear >> 2;
        lq[it] = linear & 3;
    }

    int a_m = (lane & 7) + ((lane >> 3) & 1) * 8;
    int a_k = ((lane >> 4) & 1) * 8;
    int l16 = lane & 15;
    int b_n = l16 & 7;
    int b_k = (l16 >> 3) * 8;

    uint4 ra[2], rb[2];

    // prologue: chunk 0
#pragma unroll
    for (int it = 0; it < 2; it++) {
        ra[it] = *reinterpret_cast<const uint4*>(&g_U[(size_t)(i0 + lrow[it]) * KSPL + lq[it] * 8]);
        rb[it] = *reinterpret_cast<const uint4*>(&g_V[(size_t)(j0 + lrow[it]) * KSPL + lq[it] * 8]);
    }
#pragma unroll
    for (int it = 0; it < 2; it++) {
        __half* pa = &sA[0][lrow[it]][lq[it] * 8];
        __half* pbm = &sB[0][lrow[it]][lq[it] * 8];
        *reinterpret_cast<uint2*>(pa)      = make_uint2(ra[it].x, ra[it].y);
        *reinterpret_cast<uint2*>(pa + 4)  = make_uint2(ra[it].z, ra[it].w);
        *reinterpret_cast<uint2*>(pbm)     = make_uint2(rb[it].x, rb[it].y);
        *reinterpret_cast<uint2*>(pbm + 4) = make_uint2(rb[it].z, rb[it].w);
    }
    __syncthreads();

    const int NCHUNK = KSPL / 32;   // 64
#pragma unroll 1
    for (int kc = 0; kc < NCHUNK; kc++) {
        if (kc < NCHUNK - 1) {
            int koff = (kc + 1) * 32;
#pragma unroll
            for (int it = 0; it < 2; it++) {
                ra[it] = *reinterpret_cast<const uint4*>(
                    &g_U[(size_t)(i0 + lrow[it]) * KSPL + koff + lq[it] * 8]);
                rb[it] = *reinterpret_cast<const uint4*>(
                    &g_V[(size_t)(j0 + lrow[it]) * KSPL + koff + lq[it] * 8]);
            }
        }

        {
            int buf = kc & 1;
            uint32_t baseA = (uint32_t)__cvta_generic_to_shared(&sA[buf][0][0]);
            uint32_t baseB = (uint32_t)__cvta_generic_to_shared(&sB[buf][0][0]);
#pragma unroll
            for (int ks = 0; ks < 2; ks++) {
                uint32_t af[4][4], bf[4][2];
#pragma unroll
                for (int mf = 0; mf < 4; mf++) {
                    int mm = warpM * 64 + mf * 16 + a_m;
                    int kk = ks * 16 + a_k;
                    ldsm_x4(af[mf][0], af[mf][1], af[mf][2], af[mf][3],
                            baseA + (uint32_t)(mm * SPAD + kk) * 2u);
                }
#pragma unroll
                for (int nf = 0; nf < 4; nf++) {
                    int nn = warpN * 32 + nf * 8 + b_n;
                    int kk = ks * 16 + b_k;
                    ldsm_x2(bf[nf][0], bf[nf][1],
                            baseB + (uint32_t)(nn * SPAD + kk) * 2u);
                }
#pragma unroll
                for (int mf = 0; mf < 4; mf++)
#pragma unroll
                    for (int nf = 0; nf < 4; nf++)
                        mma_fp16(acc[mf][nf][0], acc[mf][nf][1], acc[mf][nf][2], acc[mf][nf][3],
                                 af[mf][0], af[mf][1], af[mf][2], af[mf][3],
                                 bf[nf][0], bf[nf][1]);
            }
        }

        if (kc < NCHUNK - 1) {
            int buf = (kc + 1) & 1;
#pragma unroll
            for (int it = 0; it < 2; it++) {
                __half* pa = &sA[buf][lrow[it]][lq[it] * 8];
                __half* pbm = &sB[buf][lrow[it]][lq[it] * 8];
                *reinterpret_cast<uint2*>(pa)      = make_uint2(ra[it].x, ra[it].y);
                *reinterpret_cast<uint2*>(pa + 4)  = make_uint2(ra[it].z, ra[it].w);
                *reinterpret_cast<uint2*>(pbm)     = make_uint2(rb[it].x, rb[it].y);
                *reinterpret_cast<uint2*>(pbm + 4) = make_uint2(rb[it].z, rb[it].w);
            }
        }
        __syncthreads();
    }

    // epilogue: x = acc + bias ; sigmoid with exact-underflow fast path
    float bias = *pb;
    int lr = lane >> 2, lc = (lane & 3) * 2;
#pragma unroll
    for (int mf = 0; mf < 4; mf++) {
#pragma unroll
        for (int nf = 0; nf < 4; nf++) {
            int i1 = i0 + warpM * 64 + mf * 16 + lr;
            int j = j0 + warpN * 32 + nf * 8 + lc;
#pragma unroll
            for (int half = 0; half < 2; half++) {
                int i = i1 + half * 8;
                float x0 = acc[mf][nf][half * 2 + 0] + bias;
                float x1 = acc[mf][nf][half * 2 + 1] + bias;
                float2 r;
                r.x = fast_sigmoid(x0);
                r.y = fast_sigmoid(x1);
                *reinterpret_cast<float2*>(&out[(size_t)i * NNODE + j]) = r;
            }
        }
    }
}

// ---------------- launch -----------------------------------------------------
extern "C" void kernel_launch(void* const* d_in, const int* in_sizes, int n_in,
                              void* d_out, int out_size) {
    const float* z     = (const float*)d_in[0];
    const float* gamma = (const float*)d_in[1];
    const float* delta = (const float*)d_in[2];
    const float* Wz    = (const float*)d_in[3];
    const float* Wg    = (const float*)d_in[4];
    const float* Wd    = (const float*)d_in[5];
    const float* pb    = (const float*)d_in[6];
    const float* pwg   = (const float*)d_in[7];
    const float* pwd   = (const float*)d_in[8];
    float* out = (float*)d_out;

    softmax_cols<<<384, 128>>>(Wz, Wg, Wd);
    gemm_small<<<dim3(NNODE / 64, 3), 256>>>(z, gamma, delta, out);
    prep_split<<<NNODE, 128>>>(pwg, pwd);
    pair_kernel<<<dim3(NNODE / 128, NNODE / 128), 256>>>(out, pb);
}